// round 6
// baseline (speedup 1.0000x reference)
#include <cuda_runtime.h>

#define HW_    262144          // 512*512
#define C_     9
#define N_     16
#define NCH_   144             // N_*C_
#define NT_    1024            // threads per CTA
#define SLOTS_ 256             // per-thread candidate slots (256*1024 = HW_, retry-safe)

// Scratch (device globals — no allocation allowed)
__device__ unsigned long long g_cand[(size_t)NCH_ * HW_];  // per-thread regions
// Permuted bitmap: word[(f4blk<<2)|e] bit l  <->  element ((f4blk*32+l)*4+e)
__device__ unsigned g_bitmap[NCH_ * (HW_ / 32)];
__device__ unsigned g_bar_cnt;                             // grid barrier (zero-init)
__device__ unsigned g_bar_flag;

// Order-preserving float->uint key (ascending key == ascending float)
static __device__ __forceinline__ unsigned f2key(float f) {
    unsigned u = __float_as_uint(f);
    return (u & 0x80000000u) ? ~u : (u | 0x80000000u);
}

// Block-wide "find bin containing rank-from-top" over hist[0..nb), nb in {2048,1024}.
// Result: aux[0]=bin, aux[1]=remaining rank (1-indexed in bin). All NT_ threads call.
static __device__ __forceinline__ void block_find_bin(
    unsigned* hist, int nb, unsigned rank,
    unsigned* sgrp, unsigned* aux, int tid, int lane, int w)
{
    unsigned s = (nb == 2048) ? (hist[tid * 2] + hist[tid * 2 + 1]) : hist[tid];
    sgrp[tid] = s;
    __syncthreads();
    if (w == 0) {
        unsigned sup = 0;
        #pragma unroll 4
        for (int j = 0; j < 32; j++) sup += sgrp[lane * 32 + j];
        unsigned v = sup;                    // inclusive suffix scan (lane31 = top bins)
        #pragma unroll
        for (int off = 1; off < 32; off <<= 1) {
            unsigned t = __shfl_down_sync(0xffffffffu, v, off);
            if (lane + off < 32) v += t;
        }
        unsigned cumAbove = v - sup;
        bool hit = (cumAbove < rank) && (cumAbove + sup >= rank);
        unsigned bal = __ballot_sync(0xffffffffu, hit);
        int Ls = __ffs(bal) - 1;
        if (lane == Ls) {
            unsigned cum = cumAbove;
            for (int g = Ls * 32 + 31; ; g--) {
                unsigned sg = sgrp[g];
                if (cum + sg >= rank) {
                    int B = (nb == 2048) ? 2 : 1;
                    for (int b = g * B + B - 1; ; b--) {
                        unsigned h = hist[b];
                        if (cum + h >= rank) { aux[0] = (unsigned)b; aux[1] = rank - cum; break; }
                        cum += h;
                    }
                    break;
                }
                cum += sg;
            }
        }
    }
    __syncthreads();
}

__global__ void __launch_bounds__(NT_) k_fused(const float* __restrict__ inp,
                                               const float* __restrict__ ratio,
                                               const float* __restrict__ x,
                                               float* __restrict__ out)
{
    __shared__ unsigned hist[2048];
    __shared__ unsigned sgrp[NT_];
    __shared__ unsigned aux[4];        // [0]=cnt_hi / bin, [1]=m / rank

    int ch = blockIdx.x, n = ch / C_;
    int tid = threadIdx.x, w = tid >> 5, lane = tid & 31;

    // k: replicate reference f32 arithmetic exactly
    float f_p = floorf(ratio[n] * 262144.0f);
    int k = (int)floorf(f_p * 0.15f);
    bool k0 = (k <= 0);

    const float4* p = (const float4*)(inp + (size_t)ch * HW_);
    const float INF = __int_as_float(0x7F800000);

    // Analytic bracket around the k-th largest for N(0,1)-like data. Correctness
    // is guaranteed by the count-check + full-range retry, not by normality.
    float lo_f, hi_f;
    if (k0) {
        lo_f = hi_f = 1.0f;            // reference: thr = 1.0 when k == 0 (strict >, exact)
    } else {
        float q = (float)k * (1.0f / 262144.0f);
        float t = sqrtf(-2.0f * logf(q));               // A&S 26.2.23
        float z = t - (2.515517f + 0.802853f * t + 0.010328f * t * t)
                    / (1.0f + 1.432788f * t + 0.189269f * t * t + 0.001308f * t * t * t);
        float phi = 0.3989423f * expf(-0.5f * z * z);
        float delta = 0.008f + 10.0f * sqrtf((float)k) / (262144.0f * phi);
        lo_f = z - delta; hi_f = z + delta;
    }

    unsigned long long* myc = g_cand + (size_t)ch * HW_ + (size_t)tid * SLOTS_;
    unsigned* gbch = g_bitmap + (size_t)ch * 8192;
    unsigned cnt_hi, m;
    int mycap;
    for (int attempt = 0; ; attempt++) {
        if (tid == 0) { aux[0] = 0; aux[1] = 0; }
        __syncthreads();
        unsigned mycnt = 0;
        mycap = 0;
        for (int base = 0; base < HW_ / 4; base += 4 * NT_) {
            float4 v0 = p[base + tid];
            float4 v1 = p[base + NT_ + tid];
            float4 v2 = p[base + 2 * NT_ + tid];
            float4 v3 = p[base + 3 * NT_ + tid];
            #pragma unroll
            for (int j = 0; j < 4; j++) {
                float4 v = (j == 0) ? v0 : (j == 1) ? v1 : (j == 2) ? v2 : v3;
                int idx = base + j * NT_ + tid;
                bool ax = v.x > hi_f, ay = v.y > hi_f, az = v.z > hi_f, aw = v.w > hi_f;
                unsigned b0 = __ballot_sync(0xffffffffu, ax);
                unsigned b1 = __ballot_sync(0xffffffffu, ay);
                unsigned b2 = __ballot_sync(0xffffffffu, az);
                unsigned b3 = __ballot_sync(0xffffffffu, aw);
                if (lane < 4) {
                    unsigned bw = b0;
                    if (lane == 1) bw = b1; else if (lane == 2) bw = b2; else if (lane == 3) bw = b3;
                    int f4blk = ((base + j * NT_) >> 5) + w;
                    gbch[(f4blk << 2) + lane] = bw;
                    mycnt += __popc(bw);
                }
                bool cx = (v.x > lo_f) & !ax, cy = (v.y > lo_f) & !ay;
                bool cz = (v.z > lo_f) & !az, cw = (v.w > lo_f) & !aw;
                if (cx | cy | cz | cw) {            // rare (~0.2-2%)
                    if (cx) myc[mycap++] = ((unsigned long long)f2key(v.x) << 32) | (unsigned)(idx * 4 + 0);
                    if (cy) myc[mycap++] = ((unsigned long long)f2key(v.y) << 32) | (unsigned)(idx * 4 + 1);
                    if (cz) myc[mycap++] = ((unsigned long long)f2key(v.z) << 32) | (unsigned)(idx * 4 + 2);
                    if (cw) myc[mycap++] = ((unsigned long long)f2key(v.w) << 32) | (unsigned)(idx * 4 + 3);
                }
            }
        }
        // Block totals
        unsigned mc = (unsigned)mycap;
        #pragma unroll
        for (int off = 16; off; off >>= 1) {
            mycnt += __shfl_down_sync(0xffffffffu, mycnt, off);
            mc    += __shfl_down_sync(0xffffffffu, mc, off);
        }
        if (lane == 0) { atomicAdd(&aux[0], mycnt); atomicAdd(&aux[1], mc); }
        __syncthreads();
        cnt_hi = aux[0]; m = aux[1];
        if (k0) break;
        if ((cnt_hi < (unsigned)k && cnt_hi + m >= (unsigned)k) || attempt >= 1) break;
        lo_f = -INF; hi_f = INF;       // deterministic widen (count-check guarantee)
        __syncthreads();
    }

    // ---- exact threshold among candidates (11+11+10-bit radix), then fixups ----
    if (!k0) {
        unsigned r = (unsigned)k - cnt_hi;
        for (int i = tid; i < 2048; i += NT_) hist[i] = 0;
        __syncthreads();
        for (int i = 0; i < mycap; i++)
            atomicAdd(&hist[(unsigned)(myc[i] >> 32) >> 21], 1u);
        __syncthreads();
        block_find_bin(hist, 2048, r, sgrp, aux, tid, lane, w);
        unsigned bA = aux[0], rA = aux[1];
        __syncthreads();

        for (int i = tid; i < 2048; i += NT_) hist[i] = 0;
        __syncthreads();
        for (int i = 0; i < mycap; i++) {
            unsigned key = (unsigned)(myc[i] >> 32);
            if ((key >> 21) == bA) atomicAdd(&hist[(key >> 10) & 0x7FFu], 1u);
        }
        __syncthreads();
        block_find_bin(hist, 2048, rA, sgrp, aux, tid, lane, w);
        unsigned bB = aux[0], rB = aux[1];
        __syncthreads();

        for (int i = tid; i < 1024; i += NT_) hist[i] = 0;
        __syncthreads();
        for (int i = 0; i < mycap; i++) {
            unsigned key = (unsigned)(myc[i] >> 32);
            if ((key >> 21) == bA && ((key >> 10) & 0x7FFu) == bB)
                atomicAdd(&hist[key & 0x3FFu], 1u);
        }
        __syncthreads();
        block_find_bin(hist, 1024, rB, sgrp, aux, tid, lane, w);
        unsigned thrkey = (bA << 21) | (bB << 10) | aux[0];    // exact k-th largest
        __syncthreads();

        // Fixups: candidates above exact threshold -> set bit in permuted bitmap
        for (int i = 0; i < mycap; i++) {
            unsigned long long cc = myc[i];
            if ((unsigned)(cc >> 32) > thrkey) {
                unsigned pos = (unsigned)cc & 0x3FFFFu;
                unsigned f4 = pos >> 2, e = pos & 3u;
                atomicOr(&gbch[((f4 >> 5) << 2) + e], 1u << (f4 & 31u));
            }
        }
    }

    // ---- software grid barrier (all 144 CTAs resident; graph-replay safe) ----
    __threadfence();
    __syncthreads();
    if (tid == 0) {
        unsigned gen = *(volatile unsigned*)&g_bar_flag;
        unsigned t = atomicAdd(&g_bar_cnt, 1u);
        if (t == NCH_ - 1) {
            atomicExch(&g_bar_cnt, 0u);          // reset for next graph replay
            __threadfence();
            atomicAdd(&g_bar_flag, 1u);
        } else {
            while (*(volatile unsigned*)&g_bar_flag == gen) __nanosleep(64);
        }
        __threadfence();
    }
    __syncthreads();

    // ---- phase 2: warp-cooperative OR of 9 channel bitmaps, apply to x ----
    // One warp handles 32 consecutive float4s (one f4blk). 32768 chunks total.
    int gw = blockIdx.x * (NT_ / 32) + w;            // global warp id, 0..4607
    for (int chunk = gw; chunk < N_ * 2048; chunk += NCH_ * (NT_ / 32)) {
        int nn = chunk >> 11;                        // sample
        int f4blk = chunk & 2047;
        const unsigned* bmb = g_bitmap + (size_t)nn * C_ * 8192 + (f4blk << 2);
        unsigned wv = bmb[(size_t)(lane >> 2) * 8192 + (lane & 3)];   // ch=lane/4, e=lane&3
        unsigned w8 = (lane < 4) ? bmb[(size_t)8 * 8192 + lane] : 0u; // channel 8
        wv |= __shfl_xor_sync(0xffffffffu, wv, 4);   // OR over channels 0..7
        wv |= __shfl_xor_sync(0xffffffffu, wv, 8);
        wv |= __shfl_xor_sync(0xffffffffu, wv, 16);
        wv |= w8;                                    // lanes 0..3 now complete for e=lane
        unsigned b0 = __shfl_sync(0xffffffffu, wv, 0);
        unsigned b1 = __shfl_sync(0xffffffffu, wv, 1);
        unsigned b2 = __shfl_sync(0xffffffffu, wv, 2);
        unsigned b3 = __shfl_sync(0xffffffffu, wv, 3);
        int i = (nn << 16) | (f4blk << 5) | lane;    // global float4 index
        float4 xv = ((const float4*)x)[i];
        float4 o;
        o.x = ((b0 >> lane) & 1u) ? 0.0f : xv.x;
        o.y = ((b1 >> lane) & 1u) ? 0.0f : xv.y;
        o.z = ((b2 >> lane) & 1u) ? 0.0f : xv.z;
        o.w = ((b3 >> lane) & 1u) ? 0.0f : xv.w;
        ((float4*)out)[i] = o;
    }
}

extern "C" void kernel_launch(void* const* d_in, const int* in_sizes, int n_in,
                              void* d_out, int out_size) {
    const float* inp   = (const float*)d_in[0];   // [16,9,512,512]
    const float* x     = (const float*)d_in[1];   // [16,1,512,512]
    const float* ratio = (const float*)d_in[2];   // [16]
    float* out = (float*)d_out;

    k_fused<<<NCH_, NT_>>>(inp, ratio, x, out);
}

// round 7
// speedup vs baseline: 1.1674x; 1.1674x over previous
#include <cuda_runtime.h>

#define HW_    262144          // 512*512
#define C_     9
#define N_     16
#define NCH_   144             // N_*C_
#define NT_    1024            // threads per CTA
#define SLOTS_ 256             // per-thread candidate slots (256*1024 = HW_, retry-safe)

// Scratch (device globals — no allocation allowed)
__device__ unsigned long long g_cand[(size_t)NCH_ * HW_];  // per-thread regions
// Bitmap layout (per channel, 8192 words): word[ob*1024 + t], bit j*4+e
//   <-> element ((ob*8192 + j*1024 + t)*4 + e),  ob in 0..7, j in 0..7, t in 0..1023
__device__ unsigned g_bitmap[NCH_ * (HW_ / 32)];
__device__ unsigned g_bar_cnt;                             // grid barrier (zero-init)
__device__ unsigned g_bar_flag;

// Order-preserving float->uint key (ascending key == ascending float)
static __device__ __forceinline__ unsigned f2key(float f) {
    unsigned u = __float_as_uint(f);
    return (u & 0x80000000u) ? ~u : (u | 0x80000000u);
}

// Block-wide "find bin containing rank-from-top" over hist[0..nb), nb in {2048,1024}.
// Result: aux[0]=bin, aux[1]=remaining rank (1-indexed in bin). All NT_ threads call.
static __device__ __forceinline__ void block_find_bin(
    unsigned* hist, int nb, unsigned rank,
    unsigned* sgrp, unsigned* aux, int tid, int lane, int w)
{
    unsigned s = (nb == 2048) ? (hist[tid * 2] + hist[tid * 2 + 1]) : hist[tid];
    sgrp[tid] = s;
    __syncthreads();
    if (w == 0) {
        unsigned sup = 0;
        #pragma unroll 4
        for (int j = 0; j < 32; j++) sup += sgrp[lane * 32 + j];
        unsigned v = sup;                    // inclusive suffix scan (lane31 = top bins)
        #pragma unroll
        for (int off = 1; off < 32; off <<= 1) {
            unsigned t = __shfl_down_sync(0xffffffffu, v, off);
            if (lane + off < 32) v += t;
        }
        unsigned cumAbove = v - sup;
        bool hit = (cumAbove < rank) && (cumAbove + sup >= rank);
        unsigned bal = __ballot_sync(0xffffffffu, hit);
        int Ls = __ffs(bal) - 1;
        if (lane == Ls) {
            unsigned cum = cumAbove;
            for (int g = Ls * 32 + 31; ; g--) {
                unsigned sg = sgrp[g];
                if (cum + sg >= rank) {
                    int B = (nb == 2048) ? 2 : 1;
                    for (int b = g * B + B - 1; ; b--) {
                        unsigned h = hist[b];
                        if (cum + h >= rank) { aux[0] = (unsigned)b; aux[1] = rank - cum; break; }
                        cum += h;
                    }
                    break;
                }
                cum += sg;
            }
        }
    }
    __syncthreads();
}

__global__ void __launch_bounds__(NT_) k_fused(const float* __restrict__ inp,
                                               const float* __restrict__ ratio,
                                               const float* __restrict__ x,
                                               float* __restrict__ out)
{
    __shared__ unsigned hist[2048];
    __shared__ unsigned sgrp[NT_];
    __shared__ unsigned aux[4];        // [0]=cnt_hi / bin, [1]=m / rank

    int ch = blockIdx.x, n = ch / C_;
    int tid = threadIdx.x, w = tid >> 5, lane = tid & 31;

    // k: replicate reference f32 arithmetic exactly
    float f_p = floorf(ratio[n] * 262144.0f);
    int k = (int)floorf(f_p * 0.15f);
    bool k0 = (k <= 0);

    const float4* p = (const float4*)(inp + (size_t)ch * HW_);
    const float INF = __int_as_float(0x7F800000);

    // Analytic bracket around the k-th largest for N(0,1)-like data. Correctness
    // is guaranteed by the count-check + full-range retry, not by normality.
    float lo_f, hi_f;
    if (k0) {
        lo_f = hi_f = 1.0f;            // reference: thr = 1.0 when k == 0 (strict >, exact)
    } else {
        float q = (float)k * (1.0f / 262144.0f);
        float t = sqrtf(-2.0f * logf(q));               // A&S 26.2.23
        float z = t - (2.515517f + 0.802853f * t + 0.010328f * t * t)
                    / (1.0f + 1.432788f * t + 0.189269f * t * t + 0.001308f * t * t * t);
        float phi = 0.3989423f * expf(-0.5f * z * z);
        float delta = 0.008f + 10.0f * sqrtf((float)k) / (262144.0f * phi);
        lo_f = z - delta; hi_f = z + delta;
    }

    unsigned long long* myc = g_cand + (size_t)ch * HW_ + (size_t)tid * SLOTS_;
    unsigned* gbch = g_bitmap + (size_t)ch * 8192;
    unsigned cnt_hi, m;
    int mycap;
    for (int attempt = 0; ; attempt++) {
        if (tid == 0) { aux[0] = 0; aux[1] = 0; }
        __syncthreads();
        unsigned mycnt = 0;
        mycap = 0;
        #pragma unroll 1
        for (int ob = 0; ob < 8; ob++) {           // 8 outer blocks of 8*NT_ float4s
            int base = ob * 8 * NT_;
            float4 v0 = p[base + tid];
            float4 v1 = p[base + NT_ + tid];
            float4 v2 = p[base + 2 * NT_ + tid];
            float4 v3 = p[base + 3 * NT_ + tid];
            float4 v4 = p[base + 4 * NT_ + tid];
            float4 v5 = p[base + 5 * NT_ + tid];
            float4 v6 = p[base + 6 * NT_ + tid];
            float4 v7 = p[base + 7 * NT_ + tid];
            unsigned word = 0;
            #pragma unroll
            for (int j = 0; j < 8; j++) {
                float4 v = (j == 0) ? v0 : (j == 1) ? v1 : (j == 2) ? v2 : (j == 3) ? v3
                         : (j == 4) ? v4 : (j == 5) ? v5 : (j == 6) ? v6 : v7;
                unsigned hi4 = (unsigned)(v.x > hi_f) | ((unsigned)(v.y > hi_f) << 1)
                             | ((unsigned)(v.z > hi_f) << 2) | ((unsigned)(v.w > hi_f) << 3);
                unsigned lo4 = (unsigned)(v.x > lo_f) | ((unsigned)(v.y > lo_f) << 1)
                             | ((unsigned)(v.z > lo_f) << 2) | ((unsigned)(v.w > lo_f) << 3);
                word |= hi4 << (j * 4);
                unsigned cn = lo4 & ~hi4;
                if (cn) {                           // rare (~0.2-2%)
                    int idx4 = base + j * NT_ + tid;
                    if (cn & 1u) myc[mycap++] = ((unsigned long long)f2key(v.x) << 32) | (unsigned)(idx4 * 4 + 0);
                    if (cn & 2u) myc[mycap++] = ((unsigned long long)f2key(v.y) << 32) | (unsigned)(idx4 * 4 + 1);
                    if (cn & 4u) myc[mycap++] = ((unsigned long long)f2key(v.z) << 32) | (unsigned)(idx4 * 4 + 2);
                    if (cn & 8u) myc[mycap++] = ((unsigned long long)f2key(v.w) << 32) | (unsigned)(idx4 * 4 + 3);
                }
            }
            mycnt += __popc(word);
            gbch[ob * NT_ + tid] = word;            // coalesced, no cross-lane ops
        }
        // Block totals
        unsigned mc = (unsigned)mycap;
        #pragma unroll
        for (int off = 16; off; off >>= 1) {
            mycnt += __shfl_down_sync(0xffffffffu, mycnt, off);
            mc    += __shfl_down_sync(0xffffffffu, mc, off);
        }
        if (lane == 0) { atomicAdd(&aux[0], mycnt); atomicAdd(&aux[1], mc); }
        __syncthreads();
        cnt_hi = aux[0]; m = aux[1];
        if (k0) break;
        if ((cnt_hi < (unsigned)k && cnt_hi + m >= (unsigned)k) || attempt >= 1) break;
        lo_f = -INF; hi_f = INF;       // deterministic widen (count-check guarantee)
        __syncthreads();
    }

    // ---- exact threshold among candidates (11+11+10-bit radix), then fixups ----
    if (!k0) {
        unsigned r = (unsigned)k - cnt_hi;
        for (int i = tid; i < 2048; i += NT_) hist[i] = 0;
        __syncthreads();
        for (int i = 0; i < mycap; i++)
            atomicAdd(&hist[(unsigned)(myc[i] >> 32) >> 21], 1u);
        __syncthreads();
        block_find_bin(hist, 2048, r, sgrp, aux, tid, lane, w);
        unsigned bA = aux[0], rA = aux[1];
        __syncthreads();

        for (int i = tid; i < 2048; i += NT_) hist[i] = 0;
        __syncthreads();
        for (int i = 0; i < mycap; i++) {
            unsigned key = (unsigned)(myc[i] >> 32);
            if ((key >> 21) == bA) atomicAdd(&hist[(key >> 10) & 0x7FFu], 1u);
        }
        __syncthreads();
        block_find_bin(hist, 2048, rA, sgrp, aux, tid, lane, w);
        unsigned bB = aux[0], rB = aux[1];
        __syncthreads();

        for (int i = tid; i < 1024; i += NT_) hist[i] = 0;
        __syncthreads();
        for (int i = 0; i < mycap; i++) {
            unsigned key = (unsigned)(myc[i] >> 32);
            if ((key >> 21) == bA && ((key >> 10) & 0x7FFu) == bB)
                atomicAdd(&hist[key & 0x3FFu], 1u);
        }
        __syncthreads();
        block_find_bin(hist, 1024, rB, sgrp, aux, tid, lane, w);
        unsigned thrkey = (bA << 21) | (bB << 10) | aux[0];    // exact k-th largest
        __syncthreads();

        // Fixups: candidates above exact threshold -> set bit in bitmap
        for (int i = 0; i < mycap; i++) {
            unsigned long long cc = myc[i];
            if ((unsigned)(cc >> 32) > thrkey) {
                unsigned pos = (unsigned)cc & 0x3FFFFu;
                unsigned f4 = pos >> 2, e = pos & 3u;
                unsigned t  = f4 & 1023u, j = (f4 >> 10) & 7u, ob = f4 >> 13;
                atomicOr(&gbch[ob * NT_ + t], 1u << (j * 4 + e));
            }
        }
    }

    // ---- software grid barrier (all 144 CTAs resident; graph-replay safe) ----
    __threadfence();
    __syncthreads();
    if (tid == 0) {
        unsigned gen = *(volatile unsigned*)&g_bar_flag;
        unsigned t = atomicAdd(&g_bar_cnt, 1u);
        if (t == NCH_ - 1) {
            atomicExch(&g_bar_cnt, 0u);          // reset for next graph replay
            __threadfence();
            atomicAdd(&g_bar_flag, 1u);
        } else {
            while (*(volatile unsigned*)&g_bar_flag == gen) __nanosleep(64);
        }
        __threadfence();
    }
    __syncthreads();

    // ---- phase 2: per-thread OR of 9 channel words, apply to 8 float4s of x ----
    // Work item g: sample nn = g/8192, word pos wp = g%8192 (= ob*1024 + t).
    int gidx = blockIdx.x * NT_ + tid;               // 147456 threads, 131072 items
    if (gidx < N_ * 8192) {
        int nn = gidx >> 13;
        int wp = gidx & 8191;
        int ob = wp >> 10, t = wp & 1023;
        const unsigned* bm = g_bitmap + (size_t)nn * C_ * 8192 + wp;
        unsigned wrd = 0;
        #pragma unroll
        for (int c = 0; c < C_; c++) wrd |= __ldg(bm + (size_t)c * 8192);
        const float4* xp = (const float4*)x + ((size_t)nn << 16) + ob * 8192 + t;
        float4*       op = (float4*)out     + ((size_t)nn << 16) + ob * 8192 + t;
        #pragma unroll
        for (int j = 0; j < 8; j++) {
            float4 xv = xp[j * 1024];
            unsigned nib = (wrd >> (j * 4)) & 0xFu;
            float4 o;
            o.x = (nib & 1u) ? 0.0f : xv.x;
            o.y = (nib & 2u) ? 0.0f : xv.y;
            o.z = (nib & 4u) ? 0.0f : xv.z;
            o.w = (nib & 8u) ? 0.0f : xv.w;
            op[j * 1024] = o;
        }
    }
}

extern "C" void kernel_launch(void* const* d_in, const int* in_sizes, int n_in,
                              void* d_out, int out_size) {
    const float* inp   = (const float*)d_in[0];   // [16,9,512,512]
    const float* x     = (const float*)d_in[1];   // [16,1,512,512]
    const float* ratio = (const float*)d_in[2];   // [16]
    float* out = (float*)d_out;

    k_fused<<<NCH_, NT_>>>(inp, ratio, x, out);
}